// round 14
// baseline (speedup 1.0000x reference)
#include <cuda_runtime.h>
#include <cuda_bf16.h>
#include <cstdint>

#define N_NODES 100000
#define N_EDGES 1000000
#define N_TILES 782                    // ceil(100000/128)
#define FEAT4_T (N_NODES * 6)          // feature-pack domain (float4 per thread)
#define SCAN_BLOCKS 98
#define TAIL2 (FEAT4_T + N_EDGES)
#define NBINS 16

// ---- scratch (static device globals; zero-initialized, no runtime alloc) ----
__device__ __align__(16) float g_feat[N_NODES * 32];        // [n][32]: 21 data + pad; 128B/row aligned
__device__ __align__(16) float g_agg[N_TILES * 128 * 24];   // aggregated raw features
__device__ float  g_Weff[24 * 128];    // [Wu@W1a ; Wm@W1b]
__device__ float  g_beff[128];         // bu@W1a + bm@W1b + b1
__device__ unsigned long long g_degcnt[N_NODES];  // (count<<32)|deg_fx24; zero at entry/exit
__device__ float  g_dinv[N_NODES];
__device__ int    g_off[N_NODES + 1];
__device__ int    g_cursor[N_NODES];
__device__ int    g_flag[SCAN_BLOCKS]; // scan lookback; reset by k12
__device__ int    g_binh[NBINS];       // degree histogram; reset by k12
__device__ int    g_bincur[NBINS];     // bin cursors (written by scan last-block)
__device__ int    g_sdone;             // scan completion counter; reset by k12
__device__ unsigned char g_ndeg[N_NODES];
__device__ int    g_p[N_NODES];        // degree-sorted node permutation
__device__ __align__(8) float2 g_edge[N_EDGES];   // {row_as_int_bits, norm}

// ---------------------------------------------------------------------------
// K12: fused — (a) pack raw features (128B-aligned rows), (b) edge-degree
//      packed 64-bit atomics, (c) tail: Weff/beff precompute + resets.
// ---------------------------------------------------------------------------
__global__ __launch_bounds__(256) void k12(
    const float* __restrict__ ux, const float* __restrict__ mx,
    const float* __restrict__ Wu, const float* __restrict__ Wm,
    const float* __restrict__ W1, const float* __restrict__ bu,
    const float* __restrict__ bm, const float* __restrict__ b1,
    const int* __restrict__ ei, const float* __restrict__ ew) {
    int gid = blockIdx.x * blockDim.x + threadIdx.x;

    if (gid < FEAT4_T) {
        int n = gid / 6;
        int c = gid - n * 6;              // float4 chunk 0..5 of feat row
        int i0 = c * 4;
        float4 v;
        float* vp = &v.x;
#pragma unroll
        for (int q = 0; q < 4; q++) {
            int f = i0 + q;
            float x = 0.f;
            if (f < 3) x = ux[n * 3 + f];
            else if (f < 21) x = mx[n * 18 + f - 3];
            vp[q] = x;
        }
        *(float4*)&g_feat[n * 32 + i0] = v;   // stride 32: row = one 128B line
    } else if (gid < TAIL2) {
        int e = gid - FEAT4_T;
        int col = ei[N_EDGES + e];
        unsigned fx = __float2uint_rn(ew[e] * 16777216.0f);   // 2^24 fixed point
        atomicAdd(&g_degcnt[col], (1ULL << 32) | (unsigned long long)fx);
    } else {
        int t = gid - TAIL2;
        if (t < 2688) {                       // Weff[k][j], k<21
            int k = t >> 7, j = t & 127;
            float s = 0.f;
            if (k < 3) {
#pragma unroll 8
                for (int c = 0; c < 64; c++)
                    s += Wu[k * 64 + c] * W1[c * 128 + j];
            } else {
#pragma unroll 8
                for (int c = 0; c < 64; c++)
                    s += Wm[(k - 3) * 64 + c] * W1[(64 + c) * 128 + j];
            }
            g_Weff[k * 128 + j] = s;
        } else if (t < 2816) {                // beff[j]
            int j = t - 2688;
            float s = b1[j];
#pragma unroll 8
            for (int c = 0; c < 64; c++) {
                s += bu[c] * W1[c * 128 + j];
                s += bm[c] * W1[(64 + c) * 128 + j];
            }
            g_beff[j] = s;
        } else if (t < 2816 + SCAN_BLOCKS) {
            g_flag[t - 2816] = 0;
        } else if (t < 2816 + SCAN_BLOCKS + NBINS) {
            g_binh[t - 2816 - SCAN_BLOCKS] = 0;
        } else if (t == 2816 + SCAN_BLOCKS + NBINS) {
            g_sdone = 0;
        }
    }
}

// ---------------------------------------------------------------------------
// SCAN: lookback scan + dinv + degcnt reset + degree histogram. The LAST
//       block to finish (fence-protected counter) computes bin prefix.
// ---------------------------------------------------------------------------
__global__ __launch_bounds__(256) void scan_k() {
    __shared__ int ts[256];
    __shared__ int sbase;
    int t = threadIdx.x;
    int b = blockIdx.x;
    int base = b * 1024 + t * 4;

    int v[4];
    int s = 0;
#pragma unroll
    for (int i = 0; i < 4; i++) {
        int idx = base + i;
        if (idx < N_NODES) {
            unsigned long long dc = g_degcnt[idx];
            g_degcnt[idx] = 0ULL;
            v[i] = (int)(dc >> 32);
            float deg = (float)(unsigned)dc * (1.0f / 16777216.0f);
            g_dinv[idx] = rsqrtf(deg + 1.0f);
            int bin = v[i] >> 1; if (bin > NBINS - 1) bin = NBINS - 1;
            atomicAdd(&g_binh[bin], 1);
            g_ndeg[idx] = (unsigned char)(v[i] < 255 ? v[i] : 255);
        } else v[i] = 0;
        s += v[i];
    }
    ts[t] = s;
    if (t == 0) sbase = 0;
    __syncthreads();
    for (int off = 1; off < 256; off <<= 1) {
        int add = (t >= off) ? ts[t - off] : 0;
        __syncthreads();
        ts[t] += add;
        __syncthreads();
    }
    if (t == 0) atomicExch(&g_flag[b], ts[255] + 1);   // publish
    if (t < b) {                                       // poll predecessors
        int w;
        do { w = atomicAdd(&g_flag[t], 0); } while (w == 0);
        atomicAdd(&sbase, w - 1);
    }
    __syncthreads();

    int run = sbase + ts[t] - s;
#pragma unroll
    for (int i = 0; i < 4; i++) {
        int idx = base + i;
        if (idx < N_NODES) {
            g_off[idx] = run;
            g_cursor[idx] = run;
        }
        run += v[i];
    }
    if (b == 0 && t == 0) g_off[N_NODES] = N_EDGES;

    // last-finishing block builds the bin cursors (no broadcast spin)
    __syncthreads();
    if (t == 0) {
        __threadfence();
        int old = atomicAdd(&g_sdone, 1);
        if (old == SCAN_BLOCKS - 1) {
            int acc = 0;
#pragma unroll
            for (int q = 0; q < NBINS; q++) {
                int h = atomicAdd(&g_binh[q], 0);
                g_bincur[q] = acc;
                acc += h;
            }
        }
    }
}

// ---------------------------------------------------------------------------
// F: fill CSR slots with (row, norm) + assign degree-sorted node ranks.
// ---------------------------------------------------------------------------
__global__ __launch_bounds__(256) void f_fill(
    const int* __restrict__ ei, const float* __restrict__ ew) {
    int gid = blockIdx.x * blockDim.x + threadIdx.x;
    if (gid < N_EDGES) {
        int row = ei[gid];
        int col = ei[N_EDGES + gid];
        float norm = g_dinv[row] * ew[gid] * g_dinv[col];
        int pos = atomicAdd(&g_cursor[col], 1);
        g_edge[pos] = make_float2(__int_as_float(row), norm);
    } else {
        int n = gid - N_EDGES;
        if (n < N_NODES) {
            int bin = g_ndeg[n] >> 1; if (bin > NBINS - 1) bin = NBINS - 1;
            int pos = atomicAdd(&g_bincur[bin], 1);
            g_p[pos] = n;
        }
    }
}

// ---------------------------------------------------------------------------
// G6: gather RAW features, degree-sorted order (warps hold same-degree
//     nodes -> ~no max-degree divergence), 128B-aligned rows (1 line/row),
//     edge-quad software pipelining, 6 CTAs/SM.
// ---------------------------------------------------------------------------
__global__ __launch_bounds__(256, 6) void g_gather6() {
    unsigned gid = blockIdx.x * blockDim.x + threadIdx.x;
    unsigned g = gid / 6;
    int l6 = gid - g * 6;
    if (g >= N_NODES) return;
    int n = g_p[g];

    const float4* f4 = (const float4*)g_feat;   // 8 float4 per row (stride 32f)
    float din = g_dinv[n];
    float s = din * din;                        // self-loop norm
    float4 v = f4[n * 8 + l6];
    float4 a = make_float4(s * v.x, s * v.y, s * v.z, s * v.w);

    int j = g_off[n];
    int end = g_off[n + 1];
    int rem = end - j;

    float2 c0, c1, c2, c3;
    if (rem >= 4) {                             // prime the pipeline
        c0 = g_edge[j]; c1 = g_edge[j + 1];
        c2 = g_edge[j + 2]; c3 = g_edge[j + 3];
    }
    while (rem >= 4) {
        j += 4; rem -= 4;
        float2 n0, n1, n2, n3;
        if (rem >= 4) {                         // prefetch next quad NOW
            n0 = g_edge[j]; n1 = g_edge[j + 1];
            n2 = g_edge[j + 2]; n3 = g_edge[j + 3];
        }
        float4 u0 = f4[__float_as_int(c0.x) * 8 + l6];
        float4 u1 = f4[__float_as_int(c1.x) * 8 + l6];
        float4 u2 = f4[__float_as_int(c2.x) * 8 + l6];
        float4 u3 = f4[__float_as_int(c3.x) * 8 + l6];
        a.x += c0.y * u0.x + c1.y * u1.x + c2.y * u2.x + c3.y * u3.x;
        a.y += c0.y * u0.y + c1.y * u1.y + c2.y * u2.y + c3.y * u3.y;
        a.z += c0.y * u0.z + c1.y * u1.z + c2.y * u2.z + c3.y * u3.z;
        a.w += c0.y * u0.w + c1.y * u1.w + c2.y * u2.w + c3.y * u3.w;
        c0 = n0; c1 = n1; c2 = n2; c3 = n3;
    }
    for (; j < end; j++) {
        float2 ed = g_edge[j];
        float4 u = f4[__float_as_int(ed.x) * 8 + l6];
        a.x += ed.y * u.x; a.y += ed.y * u.y;
        a.z += ed.y * u.z; a.w += ed.y * u.w;
    }
    *(float4*)&g_agg[n * 24 + l6 * 4] = a;
}

// ---------------------------------------------------------------------------
// MLP via split-bf16 mma.sync.m16n8k16.
//   A = agg[128 x 24] pad K->32, hi/lo;  B = Weff^T [n=128][k=32], hi/lo.
//   D = AhBh + AhBl + AlBh (fp32 acc); out = relu(D + beff).W2 + b2.
// ---------------------------------------------------------------------------
#define MPITCH 80

__global__ __launch_bounds__(256) void mlp_mma(
    const float* __restrict__ W2, const float* __restrict__ b2,
    float* __restrict__ out) {
    __shared__ __align__(16) char s_ah[128 * MPITCH];
    __shared__ __align__(16) char s_al[128 * MPITCH];
    __shared__ __align__(16) char s_bh[128 * MPITCH];
    __shared__ __align__(16) char s_bl[128 * MPITCH];
    __shared__ float s_beff[128];
    __shared__ float s_w2[128];

    int tid = threadIdx.x;
    int w = tid >> 5;
    int lane = tid & 31;
    int tile = blockIdx.x;

    if (tid < 128) {
        s_beff[tid] = g_beff[tid];
        s_w2[tid] = W2[tid];
    }

    {
        int r = tid >> 1;
        int h16 = (tid & 1) * 16;
        const float* arow = g_agg + (size_t)tile * 3072 + r * 24;
        __nv_bfloat16* ah = (__nv_bfloat16*)(s_ah + r * MPITCH) + h16;
        __nv_bfloat16* al = (__nv_bfloat16*)(s_al + r * MPITCH) + h16;
        __nv_bfloat16* bh = (__nv_bfloat16*)(s_bh + r * MPITCH) + h16;
        __nv_bfloat16* bl = (__nv_bfloat16*)(s_bl + r * MPITCH) + h16;
#pragma unroll
        for (int q = 0; q < 16; q++) {
            int k = h16 + q;
            float av = (k < 24) ? arow[k] : 0.f;
            __nv_bfloat16 hi = __float2bfloat16(av);
            ah[q] = hi;
            al[q] = __float2bfloat16(av - __bfloat162float(hi));
            float bv = (k < 24) ? g_Weff[k * 128 + r] : 0.f;   // B[n=r][k]
            __nv_bfloat16 bhi = __float2bfloat16(bv);
            bh[q] = bhi;
            bl[q] = __float2bfloat16(bv - __bfloat162float(bhi));
        }
    }
    __syncthreads();

    float acc[16][4];
#pragma unroll
    for (int nt = 0; nt < 16; nt++)
#pragma unroll
        for (int j = 0; j < 4; j++) acc[nt][j] = 0.f;

    int gq = lane >> 2;
    int q4 = (lane & 3) * 4;
    const char* aimg[3] = {s_ah, s_ah, s_al};
    const char* bimg[3] = {s_bh, s_bl, s_bh};

#pragma unroll
    for (int ch = 0; ch < 3; ch++) {
        const char* As = aimg[ch] + (w * 16 + gq) * MPITCH;
        const char* Bs = bimg[ch] + gq * MPITCH;
#pragma unroll
        for (int ks = 0; ks < 2; ks++) {
            int kb = ks * 32 + q4;
            uint32_t a0 = *(const uint32_t*)(As + kb);
            uint32_t a1 = *(const uint32_t*)(As + 8 * MPITCH + kb);
            uint32_t a2 = *(const uint32_t*)(As + kb + 16);
            uint32_t a3 = *(const uint32_t*)(As + 8 * MPITCH + kb + 16);
#pragma unroll
            for (int nt = 0; nt < 16; nt++) {
                uint32_t b0 = *(const uint32_t*)(Bs + nt * 8 * MPITCH + kb);
                uint32_t b1v = *(const uint32_t*)(Bs + nt * 8 * MPITCH + kb + 16);
                asm volatile(
                    "mma.sync.aligned.m16n8k16.row.col.f32.bf16.bf16.f32 "
                    "{%0,%1,%2,%3}, {%4,%5,%6,%7}, {%8,%9}, {%0,%1,%2,%3};"
                    : "+f"(acc[nt][0]), "+f"(acc[nt][1]),
                      "+f"(acc[nt][2]), "+f"(acc[nt][3])
                    : "r"(a0), "r"(a1), "r"(a2), "r"(a3), "r"(b0), "r"(b1v));
            }
        }
    }

    float p0 = 0.f, p1 = 0.f;
#pragma unroll
    for (int nt = 0; nt < 16; nt++) {
        int cn = nt * 8 + (lane & 3) * 2;
        float bb0 = s_beff[cn], bb1 = s_beff[cn + 1];
        float ww0 = s_w2[cn], ww1 = s_w2[cn + 1];
        float t;
        t = acc[nt][0] + bb0; t = t > 0.f ? t : 0.f; p0 += t * ww0;
        t = acc[nt][1] + bb1; t = t > 0.f ? t : 0.f; p0 += t * ww1;
        t = acc[nt][2] + bb0; t = t > 0.f ? t : 0.f; p1 += t * ww0;
        t = acc[nt][3] + bb1; t = t > 0.f ? t : 0.f; p1 += t * ww1;
    }
    p0 += __shfl_xor_sync(0xFFFFFFFF, p0, 1);
    p0 += __shfl_xor_sync(0xFFFFFFFF, p0, 2);
    p1 += __shfl_xor_sync(0xFFFFFFFF, p1, 1);
    p1 += __shfl_xor_sync(0xFFFFFFFF, p1, 2);

    if ((lane & 3) == 0) {
        float bias2 = b2[0];
        int r0 = tile * 128 + w * 16 + gq;
        int r1 = r0 + 8;
        if (r0 < N_NODES) out[r0] = p0 + bias2;
        if (r1 < N_NODES) out[r1] = p1 + bias2;
    }
}

// ---------------------------------------------------------------------------
extern "C" void kernel_launch(void* const* d_in, const int* in_sizes, int n_in,
                              void* d_out, int out_size) {
    const float* user_x   = (const float*)d_in[0];
    const float* movie_x  = (const float*)d_in[1];
    const int*   edge_idx = (const int*)d_in[2];    // int32 (JAX x64 disabled)
    const float* edge_w   = (const float*)d_in[3];
    const float* W_user   = (const float*)d_in[4];
    const float* b_user   = (const float*)d_in[5];
    const float* W_movie  = (const float*)d_in[6];
    const float* b_movie  = (const float*)d_in[7];
    const float* W1       = (const float*)d_in[8];
    const float* b1       = (const float*)d_in[9];
    const float* W2       = (const float*)d_in[10];
    const float* b2       = (const float*)d_in[11];
    float* out = (float*)d_out;

    k12      <<<(TAIL2 + 4096 + 255) / 256, 256>>>(
        user_x, movie_x, W_user, W_movie, W1, b_user, b_movie, b1,
        edge_idx, edge_w);
    scan_k   <<<SCAN_BLOCKS, 256>>>();
    f_fill   <<<(N_EDGES + N_NODES + 255) / 256, 256>>>(edge_idx, edge_w);
    g_gather6<<<(N_NODES * 6 + 255) / 256, 256>>>();
    mlp_mma  <<<N_TILES, 256>>>(W2, b2, out);
}

// round 15
// speedup vs baseline: 1.5681x; 1.5681x over previous
#include <cuda_runtime.h>
#include <cuda_bf16.h>
#include <cstdint>

#define N_NODES 100000
#define N_EDGES 1000000
#define N_TILES 782                    // ceil(100000/128)
#define FEAT4_T (N_NODES * 6)          // feature-pack domain (float4 per thread)
#define SCAN_BLOCKS 98
#define TAIL2 (FEAT4_T + N_EDGES)

// ---- scratch (static device globals; zero-initialized, no runtime alloc) ----
__device__ __align__(16) float g_feat[N_NODES * 32];        // [n][32]: 21 data + pad; 128B rows
__device__ __align__(16) float g_agg[N_TILES * 128 * 24];   // aggregated raw features
__device__ float  g_Weff[24 * 128];    // [Wu@W1a ; Wm@W1b]
__device__ float  g_beff[128];         // bu@W1a + bm@W1b + b1
__device__ unsigned long long g_degcnt[N_NODES];  // (count<<32)|deg_fx24; zero at entry/exit
__device__ float  g_dinv[N_NODES];
__device__ int    g_off[N_NODES + 1];
__device__ int    g_cursor[N_NODES];
__device__ int    g_flag[SCAN_BLOCKS]; // scan lookback; reset by k12
__device__ __align__(8) float2 g_edge[N_EDGES];   // {row_as_int_bits, norm}

// ---------------------------------------------------------------------------
// K12: fused — (a) pack raw features into 128B-aligned rows, (b) edge-degree
//      packed 64-bit atomics, (c) tail: Weff/beff precompute + flag resets.
// ---------------------------------------------------------------------------
__global__ __launch_bounds__(256) void k12(
    const float* __restrict__ ux, const float* __restrict__ mx,
    const float* __restrict__ Wu, const float* __restrict__ Wm,
    const float* __restrict__ W1, const float* __restrict__ bu,
    const float* __restrict__ bm, const float* __restrict__ b1,
    const int* __restrict__ ei, const float* __restrict__ ew) {
    int gid = blockIdx.x * blockDim.x + threadIdx.x;

    if (gid < FEAT4_T) {
        int n = gid / 6;
        int c = gid - n * 6;              // float4 chunk 0..5 of feat row
        int i0 = c * 4;
        float4 v;
        float* vp = &v.x;
#pragma unroll
        for (int q = 0; q < 4; q++) {
            int f = i0 + q;
            float x = 0.f;
            if (f < 3) x = ux[n * 3 + f];
            else if (f < 21) x = mx[n * 18 + f - 3];
            vp[q] = x;
        }
        *(float4*)&g_feat[n * 32 + i0] = v;   // stride 32 floats: 1 line per row
    } else if (gid < TAIL2) {
        int e = gid - FEAT4_T;
        int col = ei[N_EDGES + e];
        unsigned fx = __float2uint_rn(ew[e] * 16777216.0f);   // 2^24 fixed point
        atomicAdd(&g_degcnt[col], (1ULL << 32) | (unsigned long long)fx);
    } else {
        int t = gid - TAIL2;
        if (t < 2688) {                       // Weff[k][j], k<21
            int k = t >> 7, j = t & 127;
            float s = 0.f;
            if (k < 3) {
#pragma unroll 8
                for (int c = 0; c < 64; c++)
                    s += Wu[k * 64 + c] * W1[c * 128 + j];
            } else {
#pragma unroll 8
                for (int c = 0; c < 64; c++)
                    s += Wm[(k - 3) * 64 + c] * W1[(64 + c) * 128 + j];
            }
            g_Weff[k * 128 + j] = s;
        } else if (t < 2816) {                // beff[j]
            int j = t - 2688;
            float s = b1[j];
#pragma unroll 8
            for (int c = 0; c < 64; c++) {
                s += bu[c] * W1[c * 128 + j];
                s += bm[c] * W1[(64 + c) * 128 + j];
            }
            g_beff[j] = s;
        } else if (t < 2816 + SCAN_BLOCKS) {
            g_flag[t - 2816] = 0;
        }
    }
}

// ---------------------------------------------------------------------------
// SCAN: single launch, 98 resident blocks, publish-and-sum lookback.
// ---------------------------------------------------------------------------
__global__ __launch_bounds__(256) void scan_k() {
    __shared__ int ts[256];
    __shared__ int sbase;
    int t = threadIdx.x;
    int b = blockIdx.x;
    int base = b * 1024 + t * 4;

    int v[4];
    int s = 0;
#pragma unroll
    for (int i = 0; i < 4; i++) {
        int idx = base + i;
        if (idx < N_NODES) {
            unsigned long long dc = g_degcnt[idx];
            g_degcnt[idx] = 0ULL;
            v[i] = (int)(dc >> 32);
            float deg = (float)(unsigned)dc * (1.0f / 16777216.0f);
            g_dinv[idx] = rsqrtf(deg + 1.0f);
        } else v[i] = 0;
        s += v[i];
    }
    ts[t] = s;
    if (t == 0) sbase = 0;
    __syncthreads();
    for (int off = 1; off < 256; off <<= 1) {
        int add = (t >= off) ? ts[t - off] : 0;
        __syncthreads();
        ts[t] += add;
        __syncthreads();
    }
    if (t == 0) atomicExch(&g_flag[b], ts[255] + 1);   // publish
    if (t < b) {                                       // poll predecessors
        int w;
        do { w = atomicAdd(&g_flag[t], 0); } while (w == 0);
        atomicAdd(&sbase, w - 1);
    }
    __syncthreads();

    int run = sbase + ts[t] - s;
#pragma unroll
    for (int i = 0; i < 4; i++) {
        int idx = base + i;
        if (idx < N_NODES) {
            g_off[idx] = run;
            g_cursor[idx] = run;
        }
        run += v[i];
    }
    if (b == 0 && t == 0) g_off[N_NODES] = N_EDGES;
}

// ---------------------------------------------------------------------------
// F: fill CSR slots with (row, norm).
// ---------------------------------------------------------------------------
__global__ __launch_bounds__(256) void f_fill(
    const int* __restrict__ ei, const float* __restrict__ ew) {
    int e = blockIdx.x * blockDim.x + threadIdx.x;
    if (e >= N_EDGES) return;
    int row = ei[e];
    int col = ei[N_EDGES + e];
    float norm = g_dinv[row] * ew[e] * g_dinv[col];
    int pos = atomicAdd(&g_cursor[col], 1);
    g_edge[pos] = make_float2(__int_as_float(row), norm);
}

// ---------------------------------------------------------------------------
// G7: gather RAW features (R12 structure, natural node order). Six threads
//     per node, one float4 chunk each; 128B-aligned rows -> every row access
//     is exactly one L1 line. Edge-quad software pipelining, 6 CTAs/SM.
// ---------------------------------------------------------------------------
__global__ __launch_bounds__(256, 6) void g_gather7() {
    unsigned gid = blockIdx.x * blockDim.x + threadIdx.x;
    unsigned n = gid / 6;
    int l6 = gid - n * 6;
    if (n >= N_NODES) return;

    const float4* f4 = (const float4*)g_feat;   // 8 float4 per row (stride 32f)
    float din = g_dinv[n];
    float s = din * din;                        // self-loop norm
    float4 v = f4[n * 8 + l6];
    float4 a = make_float4(s * v.x, s * v.y, s * v.z, s * v.w);

    int j = g_off[n];
    int end = g_off[n + 1];
    int rem = end - j;

    float2 c0, c1, c2, c3;
    if (rem >= 4) {                             // prime the pipeline
        c0 = g_edge[j]; c1 = g_edge[j + 1];
        c2 = g_edge[j + 2]; c3 = g_edge[j + 3];
    }
    while (rem >= 4) {
        j += 4; rem -= 4;
        float2 n0, n1, n2, n3;
        if (rem >= 4) {                         // prefetch next quad NOW
            n0 = g_edge[j]; n1 = g_edge[j + 1];
            n2 = g_edge[j + 2]; n3 = g_edge[j + 3];
        }
        float4 u0 = f4[__float_as_int(c0.x) * 8 + l6];
        float4 u1 = f4[__float_as_int(c1.x) * 8 + l6];
        float4 u2 = f4[__float_as_int(c2.x) * 8 + l6];
        float4 u3 = f4[__float_as_int(c3.x) * 8 + l6];
        a.x += c0.y * u0.x + c1.y * u1.x + c2.y * u2.x + c3.y * u3.x;
        a.y += c0.y * u0.y + c1.y * u1.y + c2.y * u2.y + c3.y * u3.y;
        a.z += c0.y * u0.z + c1.y * u1.z + c2.y * u2.z + c3.y * u3.z;
        a.w += c0.y * u0.w + c1.y * u1.w + c2.y * u2.w + c3.y * u3.w;
        c0 = n0; c1 = n1; c2 = n2; c3 = n3;
    }
    for (; j < end; j++) {
        float2 ed = g_edge[j];
        float4 u = f4[__float_as_int(ed.x) * 8 + l6];
        a.x += ed.y * u.x; a.y += ed.y * u.y;
        a.z += ed.y * u.z; a.w += ed.y * u.w;
    }
    *(float4*)&g_agg[n * 24 + l6 * 4] = a;
}

// ---------------------------------------------------------------------------
// MLP via split-bf16 mma.sync.m16n8k16.
//   A = agg[128 x 24] pad K->32, hi/lo;  B = Weff^T [n=128][k=32], hi/lo.
//   D = AhBh + AhBl + AlBh (fp32 acc); out = relu(D + beff).W2 + b2.
// ---------------------------------------------------------------------------
#define MPITCH 80

__global__ __launch_bounds__(256) void mlp_mma(
    const float* __restrict__ W2, const float* __restrict__ b2,
    float* __restrict__ out) {
    __shared__ __align__(16) char s_ah[128 * MPITCH];
    __shared__ __align__(16) char s_al[128 * MPITCH];
    __shared__ __align__(16) char s_bh[128 * MPITCH];
    __shared__ __align__(16) char s_bl[128 * MPITCH];
    __shared__ float s_beff[128];
    __shared__ float s_w2[128];

    int tid = threadIdx.x;
    int w = tid >> 5;
    int lane = tid & 31;
    int tile = blockIdx.x;

    if (tid < 128) {
        s_beff[tid] = g_beff[tid];
        s_w2[tid] = W2[tid];
    }

    {
        int r = tid >> 1;
        int h16 = (tid & 1) * 16;
        const float* arow = g_agg + (size_t)tile * 3072 + r * 24;
        __nv_bfloat16* ah = (__nv_bfloat16*)(s_ah + r * MPITCH) + h16;
        __nv_bfloat16* al = (__nv_bfloat16*)(s_al + r * MPITCH) + h16;
        __nv_bfloat16* bh = (__nv_bfloat16*)(s_bh + r * MPITCH) + h16;
        __nv_bfloat16* bl = (__nv_bfloat16*)(s_bl + r * MPITCH) + h16;
#pragma unroll
        for (int q = 0; q < 16; q++) {
            int k = h16 + q;
            float av = (k < 24) ? arow[k] : 0.f;
            __nv_bfloat16 hi = __float2bfloat16(av);
            ah[q] = hi;
            al[q] = __float2bfloat16(av - __bfloat162float(hi));
            float bv = (k < 24) ? g_Weff[k * 128 + r] : 0.f;   // B[n=r][k]
            __nv_bfloat16 bhi = __float2bfloat16(bv);
            bh[q] = bhi;
            bl[q] = __float2bfloat16(bv - __bfloat162float(bhi));
        }
    }
    __syncthreads();

    float acc[16][4];
#pragma unroll
    for (int nt = 0; nt < 16; nt++)
#pragma unroll
        for (int j = 0; j < 4; j++) acc[nt][j] = 0.f;

    int gq = lane >> 2;
    int q4 = (lane & 3) * 4;
    const char* aimg[3] = {s_ah, s_ah, s_al};
    const char* bimg[3] = {s_bh, s_bl, s_bh};

#pragma unroll
    for (int ch = 0; ch < 3; ch++) {
        const char* As = aimg[ch] + (w * 16 + gq) * MPITCH;
        const char* Bs = bimg[ch] + gq * MPITCH;
#pragma unroll
        for (int ks = 0; ks < 2; ks++) {
            int kb = ks * 32 + q4;
            uint32_t a0 = *(const uint32_t*)(As + kb);
            uint32_t a1 = *(const uint32_t*)(As + 8 * MPITCH + kb);
            uint32_t a2 = *(const uint32_t*)(As + kb + 16);
            uint32_t a3 = *(const uint32_t*)(As + 8 * MPITCH + kb + 16);
#pragma unroll
            for (int nt = 0; nt < 16; nt++) {
                uint32_t b0 = *(const uint32_t*)(Bs + nt * 8 * MPITCH + kb);
                uint32_t b1v = *(const uint32_t*)(Bs + nt * 8 * MPITCH + kb + 16);
                asm volatile(
                    "mma.sync.aligned.m16n8k16.row.col.f32.bf16.bf16.f32 "
                    "{%0,%1,%2,%3}, {%4,%5,%6,%7}, {%8,%9}, {%0,%1,%2,%3};"
                    : "+f"(acc[nt][0]), "+f"(acc[nt][1]),
                      "+f"(acc[nt][2]), "+f"(acc[nt][3])
                    : "r"(a0), "r"(a1), "r"(a2), "r"(a3), "r"(b0), "r"(b1v));
            }
        }
    }

    float p0 = 0.f, p1 = 0.f;
#pragma unroll
    for (int nt = 0; nt < 16; nt++) {
        int cn = nt * 8 + (lane & 3) * 2;
        float bb0 = s_beff[cn], bb1 = s_beff[cn + 1];
        float ww0 = s_w2[cn], ww1 = s_w2[cn + 1];
        float t;
        t = acc[nt][0] + bb0; t = t > 0.f ? t : 0.f; p0 += t * ww0;
        t = acc[nt][1] + bb1; t = t > 0.f ? t : 0.f; p0 += t * ww1;
        t = acc[nt][2] + bb0; t = t > 0.f ? t : 0.f; p1 += t * ww0;
        t = acc[nt][3] + bb1; t = t > 0.f ? t : 0.f; p1 += t * ww1;
    }
    p0 += __shfl_xor_sync(0xFFFFFFFF, p0, 1);
    p0 += __shfl_xor_sync(0xFFFFFFFF, p0, 2);
    p1 += __shfl_xor_sync(0xFFFFFFFF, p1, 1);
    p1 += __shfl_xor_sync(0xFFFFFFFF, p1, 2);

    if ((lane & 3) == 0) {
        float bias2 = b2[0];
        int r0 = tile * 128 + w * 16 + gq;
        int r1 = r0 + 8;
        if (r0 < N_NODES) out[r0] = p0 + bias2;
        if (r1 < N_NODES) out[r1] = p1 + bias2;
    }
}

// ---------------------------------------------------------------------------
extern "C" void kernel_launch(void* const* d_in, const int* in_sizes, int n_in,
                              void* d_out, int out_size) {
    const float* user_x   = (const float*)d_in[0];
    const float* movie_x  = (const float*)d_in[1];
    const int*   edge_idx = (const int*)d_in[2];    // int32 (JAX x64 disabled)
    const float* edge_w   = (const float*)d_in[3];
    const float* W_user   = (const float*)d_in[4];
    const float* b_user   = (const float*)d_in[5];
    const float* W_movie  = (const float*)d_in[6];
    const float* b_movie  = (const float*)d_in[7];
    const float* W1       = (const float*)d_in[8];
    const float* b1       = (const float*)d_in[9];
    const float* W2       = (const float*)d_in[10];
    const float* b2       = (const float*)d_in[11];
    float* out = (float*)d_out;

    k12      <<<(TAIL2 + 4096 + 255) / 256, 256>>>(
        user_x, movie_x, W_user, W_movie, W1, b_user, b_movie, b1,
        edge_idx, edge_w);
    scan_k   <<<SCAN_BLOCKS, 256>>>();
    f_fill   <<<(N_EDGES + 255) / 256, 256>>>(edge_idx, edge_w);
    g_gather7<<<(N_NODES * 6 + 255) / 256, 256>>>();
    mlp_mma  <<<N_TILES, 256>>>(W2, b2, out);
}